// round 1
// baseline (speedup 1.0000x reference)
#include <cuda_runtime.h>
#include <stdint.h>

// Problem geometry: image (32,3,512,512) f32; noise subbands (32,3,256,256) x4.
#define N_NOISE  6291456      // 32*3*256*256
#define N_TOTAL  25165824     // 32*3*512*512
#define LO_F     (-0.99999994f)   // np.nextafter(-1, 0) in f32

// Scratch (static __device__ allocation is allowed; cudaMalloc is not)
__device__ float    g_noise[4ull * N_NOISE];   // ~100.7 MB
__device__ float    g_enc[N_TOTAL];            // ~100.7 MB
__device__ unsigned g_maxbits[4];              // max|n| per subband, as raw f32 bits (nonneg -> monotonic)
__device__ unsigned g_bmin[32];                // per-batch min, order-preserving uint encoding
__device__ unsigned g_bmax[32];                // per-batch max

// ---------------- Threefry-2x32 (exactly JAX's schedule) ----------------
__host__ __device__ __forceinline__ void tf2x32(unsigned k0, unsigned k1,
                                                unsigned x0, unsigned x1,
                                                unsigned &o0, unsigned &o1) {
    unsigned ks2 = k0 ^ k1 ^ 0x1BD11BDAu;
    x0 += k0; x1 += k1;
#define TFR(r) { x0 += x1; x1 = (x1 << (r)) | (x1 >> (32 - (r))); x1 ^= x0; }
    TFR(13) TFR(15) TFR(26) TFR(6)
    x0 += k1;  x1 += ks2 + 1u;
    TFR(17) TFR(29) TFR(16) TFR(24)
    x0 += ks2; x1 += k0 + 2u;
    TFR(13) TFR(15) TFR(26) TFR(6)
    x0 += k0;  x1 += k1 + 3u;
    TFR(17) TFR(29) TFR(16) TFR(24)
    x0 += k1;  x1 += ks2 + 4u;
    TFR(13) TFR(15) TFR(26) TFR(6)
    x0 += ks2; x1 += k0 + 5u;
#undef TFR
    o0 = x0; o1 = x1;
}

// ---------------- XLA f32 erf_inv (Giles polynomial, as in xla math.cc) ----------------
__device__ __forceinline__ float erfinv_xla(float x) {
    float w = -log1pf(-x * x);
    float p;
    if (w < 5.0f) {
        w = w - 2.5f;
        p =                2.81022636e-08f;
        p = fmaf(p, w,     3.43273939e-07f);
        p = fmaf(p, w,    -3.5233877e-06f);
        p = fmaf(p, w,    -4.39150654e-06f);
        p = fmaf(p, w,     0.00021858087f);
        p = fmaf(p, w,    -0.00125372503f);
        p = fmaf(p, w,    -0.00417768164f);
        p = fmaf(p, w,     0.246640727f);
        p = fmaf(p, w,     1.50140941f);
    } else {
        w = sqrtf(w) - 3.0f;
        p =               -0.000200214257f;
        p = fmaf(p, w,     0.000100950558f);
        p = fmaf(p, w,     0.00134934322f);
        p = fmaf(p, w,    -0.00367342844f);
        p = fmaf(p, w,     0.00573950773f);
        p = fmaf(p, w,    -0.0076224613f);
        p = fmaf(p, w,     0.00943887047f);
        p = fmaf(p, w,     1.00167406f);
        p = fmaf(p, w,     2.83297682f);
    }
    return p * x;
}

// Order-preserving float<->uint encoding for signed min/max atomics
__device__ __forceinline__ unsigned fenc(float f) {
    unsigned u = __float_as_uint(f);
    return (u & 0x80000000u) ? ~u : (u | 0x80000000u);
}
__device__ __forceinline__ float fdec(unsigned u) {
    return __uint_as_float((u & 0x80000000u) ? (u ^ 0x80000000u) : ~u);
}

// ---------------- K0: reset reduction cells (graph is replayed; no stale state) ----------------
__global__ void k_init() {
    int t = threadIdx.x;
    if (t < 4)  g_maxbits[t] = 0u;
    if (t < 32) { g_bmin[t] = 0xFFFFFFFFu; g_bmax[t] = 0u; }
}

// ---------------- K1: generate noise (JAX partitionable threefry), write + max|n| ----------------
// grid (6144, 4), block 256; each thread 4 samples (grid-stride by N_NOISE/4 keeps stores coalesced)
__global__ void __launch_bounds__(256) k_noise(unsigned k00, unsigned k01,
                                               unsigned k10, unsigned k11,
                                               unsigned k20, unsigned k21,
                                               unsigned k30, unsigned k31) {
    const int t = blockIdx.y;
    const unsigned kk0 = (t == 0) ? k00 : (t == 1) ? k10 : (t == 2) ? k20 : k30;
    const unsigned kk1 = (t == 0) ? k01 : (t == 1) ? k11 : (t == 2) ? k21 : k31;
    float* dst = g_noise + (size_t)t * N_NOISE;

    unsigned base = blockIdx.x * 256u + threadIdx.x;
    float lmax = 0.0f;
#pragma unroll
    for (int s = 0; s < 4; ++s) {
        unsigned i = base + (unsigned)s * (N_NOISE / 4);
        unsigned o0, o1;
        tf2x32(kk0, kk1, 0u, i, o0, o1);          // counts = (hi=0, lo=i)
        unsigned bits = o0 ^ o1;                   // partitionable 32-bit fold
        float f = __uint_as_float((bits >> 9) | 0x3F800000u) - 1.0f;  // [0,1)
        float u = fmaf(f, 2.0f, LO_F);             // maxval-minval rounds to exactly 2.0f
        u = fmaxf(u, LO_F);
        float n = 1.41421356237f * erfinv_xla(u);  // sqrt(2) as f32 = 0x3FB504F3
        dst[i] = n;
        lmax = fmaxf(lmax, fabsf(n));
    }
    // warp + block max reduction, then one atomic per block
#pragma unroll
    for (int off = 16; off; off >>= 1)
        lmax = fmaxf(lmax, __shfl_xor_sync(0xFFFFFFFFu, lmax, off));
    __shared__ float smx[8];
    int w = threadIdx.x >> 5, l = threadIdx.x & 31;
    if (l == 0) smx[w] = lmax;
    __syncthreads();
    if (threadIdx.x == 0) {
        float m = smx[0];
#pragma unroll
        for (int j = 1; j < 8; ++j) m = fmaxf(m, smx[j]);
        atomicMax(&g_maxbits[t], __float_as_uint(m));  // nonneg floats: bits are monotonic
    }
}

// ---------------- K2: enc = image + idwt(noise/(max+eps)); per-batch min/max ----------------
// One thread per 2x2 pixel quad. grid 24576 blocks x 256 threads = 6291456 quads.
__global__ void __launch_bounds__(256) k_enc(const float* __restrict__ img) {
    unsigned q  = blockIdx.x * 256u + threadIdx.x;       // quad id
    unsigned wh = q & 255u;
    unsigned hh = (q >> 8) & 255u;
    unsigned pl = q >> 16;                               // plane = b*3+c, < 96

    // normalizers (uniform across grid; L1-broadcast loads)
    float iLL = 1.0f / (__uint_as_float(g_maxbits[0]) + 1e-8f);
    float iLH = 1.0f / (__uint_as_float(g_maxbits[1]) + 1e-8f);
    float iHL = 1.0f / (__uint_as_float(g_maxbits[2]) + 1e-8f);
    float iHH = 1.0f / (__uint_as_float(g_maxbits[3]) + 1e-8f);

    float nLL = g_noise[(size_t)0 * N_NOISE + q] * iLL;
    float nLH = g_noise[(size_t)1 * N_NOISE + q] * iLH;
    float nHL = g_noise[(size_t)2 * N_NOISE + q] * iHL;
    float nHH = g_noise[(size_t)3 * N_NOISE + q] * iHH;

    float s0 = nLL + nLH, s1 = nHL + nHH;
    float d0 = nLL - nLH, d1 = nHL - nHH;
    float na = (s0 + s1) * 0.5f;
    float nb = (s0 - s1) * 0.5f;
    float nc = (d0 + d1) * 0.5f;
    float nd = (d0 - d1) * 0.5f;

    size_t ibase = (size_t)pl * 262144u + (size_t)hh * 1024u + (size_t)wh * 2u;
    float2 ab = *reinterpret_cast<const float2*>(img + ibase);
    float2 cd = *reinterpret_cast<const float2*>(img + ibase + 512u);

    float ea = ab.x + na, eb = ab.y + nb;
    float ec = cd.x + nc, ed = cd.y + nd;

    *reinterpret_cast<float2*>(g_enc + ibase)        = make_float2(ea, eb);
    *reinterpret_cast<float2*>(g_enc + ibase + 512u) = make_float2(ec, ed);

    // per-batch min/max (each block lives entirely inside one plane -> one batch)
    float lmin = fminf(fminf(ea, eb), fminf(ec, ed));
    float lmax = fmaxf(fmaxf(ea, eb), fmaxf(ec, ed));
#pragma unroll
    for (int off = 16; off; off >>= 1) {
        lmin = fminf(lmin, __shfl_xor_sync(0xFFFFFFFFu, lmin, off));
        lmax = fmaxf(lmax, __shfl_xor_sync(0xFFFFFFFFu, lmax, off));
    }
    __shared__ float smn[8], smx[8];
    int w = threadIdx.x >> 5, l = threadIdx.x & 31;
    if (l == 0) { smn[w] = lmin; smx[w] = lmax; }
    __syncthreads();
    if (threadIdx.x == 0) {
        float mn = smn[0], mx = smx[0];
#pragma unroll
        for (int j = 1; j < 8; ++j) { mn = fminf(mn, smn[j]); mx = fmaxf(mx, smx[j]); }
        int b = (int)((blockIdx.x >> 8) / 3);   // 256 blocks per plane, 3 planes per batch
        atomicMin(&g_bmin[b], fenc(mn));
        atomicMax(&g_bmax[b], fenc(mx));
    }
}

// ---------------- K3: out = (enc - min) / max(max-min, eps) ----------------
// float4 per thread; 768 blocks per batch (exact).
__global__ void __launch_bounds__(256) k_out(float* __restrict__ out) {
    unsigned i = blockIdx.x * 256u + threadIdx.x;   // float4 index < 6291456
    int b = (int)(blockIdx.x / 768u);
    float mn = fdec(g_bmin[b]);
    float mx = fdec(g_bmax[b]);
    float inv = 1.0f / fmaxf(mx - mn, 1e-8f);
    float4 e = reinterpret_cast<const float4*>(g_enc)[i];
    float4 r;
    r.x = (e.x - mn) * inv;
    r.y = (e.y - mn) * inv;
    r.z = (e.z - mn) * inv;
    r.w = (e.w - mn) * inv;
    reinterpret_cast<float4*>(out)[i] = r;
}

extern "C" void kernel_launch(void* const* d_in, const int* in_sizes, int n_in,
                              void* d_out, int out_size) {
    const float* img = (const float*)d_in[0];
    float* out = (float*)d_out;

    // jax.random.split(jax.random.key(123), 4), threefry_partitionable:
    // subkey_t = (o0, o1) of threefry2x32(key=(0,123), counts=(0, t))
    unsigned keys[8];
    for (unsigned t = 0; t < 4; ++t) {
        unsigned o0, o1;
        tf2x32(0u, 123u, 0u, t, o0, o1);
        keys[2 * t] = o0; keys[2 * t + 1] = o1;
    }

    k_init<<<1, 64>>>();
    dim3 g1(6144, 4);
    k_noise<<<g1, 256>>>(keys[0], keys[1], keys[2], keys[3],
                         keys[4], keys[5], keys[6], keys[7]);
    k_enc<<<24576, 256>>>(img);
    k_out<<<24576, 256>>>(out);
}

// round 4
// speedup vs baseline: 1.2385x; 1.2385x over previous
#include <cuda_runtime.h>
#include <cuda_fp16.h>
#include <stdint.h>

// Problem geometry: image (32,3,512,512) f32; noise subbands (32,3,256,256) x4.
#define N_NOISE  6291456      // 32*3*256*256
#define N_TOTAL  25165824     // 32*3*512*512
#define LO_F     (-0.99999994f)   // np.nextafter(-1, 0) in f32

// Scratch (static __device__ allocation is allowed; cudaMalloc is not)
__device__ __half   g_noise_h[4ull * N_NOISE]; // ~50.3 MB
__device__ unsigned g_maxbits[4];              // max|n| per subband, raw f32 bits (nonneg -> monotonic)
__device__ unsigned g_bmin[32];                // per-batch min, order-preserving uint encoding
__device__ unsigned g_bmax[32];                // per-batch max

// ---------------- Threefry-2x32 (exactly JAX's schedule) ----------------
__host__ __device__ __forceinline__ void tf2x32(unsigned k0, unsigned k1,
                                                unsigned x0, unsigned x1,
                                                unsigned &o0, unsigned &o1) {
    unsigned ks2 = k0 ^ k1 ^ 0x1BD11BDAu;
    x0 += k0; x1 += k1;
#define TFR(r) { x0 += x1; x1 = (x1 << (r)) | (x1 >> (32 - (r))); x1 ^= x0; }
    TFR(13) TFR(15) TFR(26) TFR(6)
    x0 += k1;  x1 += ks2 + 1u;
    TFR(17) TFR(29) TFR(16) TFR(24)
    x0 += ks2; x1 += k0 + 2u;
    TFR(13) TFR(15) TFR(26) TFR(6)
    x0 += k0;  x1 += k1 + 3u;
    TFR(17) TFR(29) TFR(16) TFR(24)
    x0 += k1;  x1 += ks2 + 4u;
    TFR(13) TFR(15) TFR(26) TFR(6)
    x0 += ks2; x1 += k0 + 5u;
#undef TFR
    o0 = x0; o1 = x1;
}

// ---------------- erf_inv (Giles polynomial; fast-log variant) ----------------
// fmaf(-x,x,1) computes 1-x^2 with a single rounding (no cancellation), then
// MUFU-based __logf. Max deviation from log1pf path ~1e-7 absolute in w -> far
// below the 1e-3 output tolerance.
__device__ __forceinline__ float erfinv_fast(float x) {
    float w = -__logf(fmaf(-x, x, 1.0f));
    float p;
    if (w < 5.0f) {
        w = w - 2.5f;
        p =                2.81022636e-08f;
        p = fmaf(p, w,     3.43273939e-07f);
        p = fmaf(p, w,    -3.5233877e-06f);
        p = fmaf(p, w,    -4.39150654e-06f);
        p = fmaf(p, w,     0.00021858087f);
        p = fmaf(p, w,    -0.00125372503f);
        p = fmaf(p, w,    -0.00417768164f);
        p = fmaf(p, w,     0.246640727f);
        p = fmaf(p, w,     1.50140941f);
    } else {
        w = sqrtf(w) - 3.0f;
        p =               -0.000200214257f;
        p = fmaf(p, w,     0.000100950558f);
        p = fmaf(p, w,     0.00134934322f);
        p = fmaf(p, w,    -0.00367342844f);
        p = fmaf(p, w,     0.00573950773f);
        p = fmaf(p, w,    -0.0076224613f);
        p = fmaf(p, w,     0.00943887047f);
        p = fmaf(p, w,     1.00167406f);
        p = fmaf(p, w,     2.83297682f);
    }
    return p * x;
}

// Order-preserving float<->uint encoding for signed min/max atomics
__device__ __forceinline__ unsigned fenc(float f) {
    unsigned u = __float_as_uint(f);
    return (u & 0x80000000u) ? ~u : (u | 0x80000000u);
}
__device__ __forceinline__ float fdec(unsigned u) {
    return __uint_as_float((u & 0x80000000u) ? (u ^ 0x80000000u) : ~u);
}

// ---------------- K0: reset reduction cells (graph replay safe) ----------------
__global__ void k_init() {
    int t = threadIdx.x;
    if (t < 4)  g_maxbits[t] = 0u;
    if (t < 32) { g_bmin[t] = 0xFFFFFFFFu; g_bmax[t] = 0u; }
}

// ---------------- K1: generate noise (fp16 store) + per-subband max|n| ----------------
// grid (6144, 4), block 256; 4 samples/thread strided by N/4 (coalesced).
__global__ void __launch_bounds__(256) k_noise(unsigned k00, unsigned k01,
                                               unsigned k10, unsigned k11,
                                               unsigned k20, unsigned k21,
                                               unsigned k30, unsigned k31) {
    const int t = blockIdx.y;
    const unsigned kk0 = (t == 0) ? k00 : (t == 1) ? k10 : (t == 2) ? k20 : k30;
    const unsigned kk1 = (t == 0) ? k01 : (t == 1) ? k11 : (t == 2) ? k21 : k31;
    __half* dst = g_noise_h + (size_t)t * N_NOISE;

    unsigned base = blockIdx.x * 256u + threadIdx.x;
    float lmax = 0.0f;
#pragma unroll
    for (int s = 0; s < 4; ++s) {
        unsigned i = base + (unsigned)s * (N_NOISE / 4);
        unsigned o0, o1;
        tf2x32(kk0, kk1, 0u, i, o0, o1);          // counts = (hi=0, lo=i)
        unsigned bits = o0 ^ o1;                   // partitionable 32-bit fold
        float f = __uint_as_float((bits >> 9) | 0x3F800000u) - 1.0f;  // [0,1)
        float u = fmaf(f, 2.0f, LO_F);
        u = fmaxf(u, LO_F);
        float n = 1.41421356237f * erfinv_fast(u);
        dst[i] = __float2half_rn(n);
        lmax = fmaxf(lmax, fabsf(n));
    }
#pragma unroll
    for (int off = 16; off; off >>= 1)
        lmax = fmaxf(lmax, __shfl_xor_sync(0xFFFFFFFFu, lmax, off));
    __shared__ float smx[8];
    int w = threadIdx.x >> 5, l = threadIdx.x & 31;
    if (l == 0) smx[w] = lmax;
    __syncthreads();
    if (threadIdx.x == 0) {
        float m = smx[0];
#pragma unroll
        for (int j = 1; j < 8; ++j) m = fmaxf(m, smx[j]);
        atomicMax(&g_maxbits[t], __float_as_uint(m));  // nonneg: f32 bits monotonic
    }
}

// Shared quad-pair computation: given pair index p (2 quads), produce the 8 enc
// values. Layout: quad q -> (pl, hh, wh); img 2x2 at rows 2hh,2hh+1, cols 2wh..
struct EncPair {
    float4 r0;   // row 2hh  : a0 b0 a1 b1
    float4 r1;   // row 2hh+1: c0 d0 c1 d1
    size_t ibase;
    unsigned pl;
};

__device__ __forceinline__ EncPair compute_enc_pair(const float* __restrict__ img,
                                                    unsigned p) {
    unsigned q0 = p * 2u;
    unsigned wh0 = q0 & 255u;
    unsigned hh  = (q0 >> 8) & 255u;
    unsigned pl  = q0 >> 16;

    float iLL = 1.0f / (__uint_as_float(g_maxbits[0]) + 1e-8f);
    float iLH = 1.0f / (__uint_as_float(g_maxbits[1]) + 1e-8f);
    float iHL = 1.0f / (__uint_as_float(g_maxbits[2]) + 1e-8f);
    float iHH = 1.0f / (__uint_as_float(g_maxbits[3]) + 1e-8f);

    float2 LL = __half22float2(*reinterpret_cast<const __half2*>(g_noise_h + (size_t)0 * N_NOISE + q0));
    float2 LH = __half22float2(*reinterpret_cast<const __half2*>(g_noise_h + (size_t)1 * N_NOISE + q0));
    float2 HL = __half22float2(*reinterpret_cast<const __half2*>(g_noise_h + (size_t)2 * N_NOISE + q0));
    float2 HH = __half22float2(*reinterpret_cast<const __half2*>(g_noise_h + (size_t)3 * N_NOISE + q0));

    size_t ibase = (size_t)pl * 262144u + (size_t)hh * 1024u + (size_t)wh0 * 2u;
    float4 i0 = *reinterpret_cast<const float4*>(img + ibase);          // a0 b0 a1 b1
    float4 i1 = *reinterpret_cast<const float4*>(img + ibase + 512u);   // c0 d0 c1 d1

    EncPair e;
    e.ibase = ibase; e.pl = pl;
    // quad 0
    {
        float nLL = LL.x * iLL, nLH = LH.x * iLH, nHL = HL.x * iHL, nHH = HH.x * iHH;
        float s0 = nLL + nLH, s1 = nHL + nHH;
        float d0 = nLL - nLH, d1 = nHL - nHH;
        e.r0.x = i0.x + (s0 + s1) * 0.5f;
        e.r0.y = i0.y + (s0 - s1) * 0.5f;
        e.r1.x = i1.x + (d0 + d1) * 0.5f;
        e.r1.y = i1.y + (d0 - d1) * 0.5f;
    }
    // quad 1
    {
        float nLL = LL.y * iLL, nLH = LH.y * iLH, nHL = HL.y * iHL, nHH = HH.y * iHH;
        float s0 = nLL + nLH, s1 = nHL + nHH;
        float d0 = nLL - nLH, d1 = nHL - nHH;
        e.r0.z = i0.z + (s0 + s1) * 0.5f;
        e.r0.w = i0.w + (s0 - s1) * 0.5f;
        e.r1.z = i1.z + (d0 + d1) * 0.5f;
        e.r1.w = i1.w + (d0 - d1) * 0.5f;
    }
    return e;
}

// ---------------- K2: per-batch min/max of enc (no enc store) ----------------
// 2 quads/thread; grid 12288 x 256. 128 blocks per plane -> batch = blockIdx.x/384.
__global__ void __launch_bounds__(256) k_minmax(const float* __restrict__ img) {
    unsigned p = blockIdx.x * 256u + threadIdx.x;
    EncPair e = compute_enc_pair(img, p);

    float lmin = fminf(fminf(fminf(e.r0.x, e.r0.y), fminf(e.r0.z, e.r0.w)),
                       fminf(fminf(e.r1.x, e.r1.y), fminf(e.r1.z, e.r1.w)));
    float lmax = fmaxf(fmaxf(fmaxf(e.r0.x, e.r0.y), fmaxf(e.r0.z, e.r0.w)),
                       fmaxf(fmaxf(e.r1.x, e.r1.y), fmaxf(e.r1.z, e.r1.w)));
#pragma unroll
    for (int off = 16; off; off >>= 1) {
        lmin = fminf(lmin, __shfl_xor_sync(0xFFFFFFFFu, lmin, off));
        lmax = fmaxf(lmax, __shfl_xor_sync(0xFFFFFFFFu, lmax, off));
    }
    __shared__ float smn[8], smx[8];
    int w = threadIdx.x >> 5, l = threadIdx.x & 31;
    if (l == 0) { smn[w] = lmin; smx[w] = lmax; }
    __syncthreads();
    if (threadIdx.x == 0) {
        float mn = smn[0], mx = smx[0];
#pragma unroll
        for (int j = 1; j < 8; ++j) { mn = fminf(mn, smn[j]); mx = fmaxf(mx, smx[j]); }
        int b = (int)(blockIdx.x / 384u);   // 128 blocks/plane * 3 planes/batch
        atomicMin(&g_bmin[b], fenc(mn));
        atomicMax(&g_bmax[b], fenc(mx));
    }
}

// ---------------- K3: recompute enc, normalize, write out ----------------
__global__ void __launch_bounds__(256) k_out(const float* __restrict__ img,
                                             float* __restrict__ out) {
    unsigned p = blockIdx.x * 256u + threadIdx.x;
    EncPair e = compute_enc_pair(img, p);

    int b = (int)(e.pl / 3u);
    float mn  = fdec(g_bmin[b]);
    float mx  = fdec(g_bmax[b]);
    float inv = 1.0f / fmaxf(mx - mn, 1e-8f);

    float4 o0, o1;
    o0.x = (e.r0.x - mn) * inv;  o0.y = (e.r0.y - mn) * inv;
    o0.z = (e.r0.z - mn) * inv;  o0.w = (e.r0.w - mn) * inv;
    o1.x = (e.r1.x - mn) * inv;  o1.y = (e.r1.y - mn) * inv;
    o1.z = (e.r1.z - mn) * inv;  o1.w = (e.r1.w - mn) * inv;

    *reinterpret_cast<float4*>(out + e.ibase)        = o0;
    *reinterpret_cast<float4*>(out + e.ibase + 512u) = o1;
}

extern "C" void kernel_launch(void* const* d_in, const int* in_sizes, int n_in,
                              void* d_out, int out_size) {
    const float* img = (const float*)d_in[0];
    float* out = (float*)d_out;

    // jax.random.split(jax.random.key(123), 4), threefry_partitionable
    unsigned keys[8];
    for (unsigned t = 0; t < 4; ++t) {
        unsigned o0, o1;
        tf2x32(0u, 123u, 0u, t, o0, o1);
        keys[2 * t] = o0; keys[2 * t + 1] = o1;
    }

    k_init<<<1, 64>>>();
    dim3 g1(6144, 4);
    k_noise<<<g1, 256>>>(keys[0], keys[1], keys[2], keys[3],
                         keys[4], keys[5], keys[6], keys[7]);
    k_minmax<<<12288, 256>>>(img);
    k_out<<<12288, 256>>>(img, out);
}